// round 12
// baseline (speedup 1.0000x reference)
#include <cuda_runtime.h>
#include <cuda_fp16.h>
#include <stdint.h>
#include <math.h>

#define B_ROWS 8192
#define ROWS_PAD 8448
#define D_DIM 1024
#define HR_DIM 512
#define HE_DIM 4096
#define HF_DIM 2048

// ---------------- PTX helpers (base sm_103-safe) ----------------
__device__ __forceinline__ uint32_t smem_u32(const void* p) {
    uint32_t a;
    asm("{ .reg .u64 t; cvta.to.shared.u64 t, %1; cvt.u32.u64 %0, t; }" : "=r"(a) : "l"(p));
    return a;
}
__device__ __forceinline__ void cp16(uint32_t dst, const void* src) {
    asm volatile("cp.async.cg.shared.global [%0], [%1], 16;" :: "r"(dst), "l"(src));
}
#define CP_COMMIT asm volatile("cp.async.commit_group;" ::: "memory")

__device__ __forceinline__ void ldsm4(uint32_t& r0, uint32_t& r1, uint32_t& r2, uint32_t& r3,
                                      uint32_t a) {
    asm volatile("ldmatrix.sync.aligned.m8n8.x4.shared.b16 {%0,%1,%2,%3}, [%4];"
                 : "=r"(r0), "=r"(r1), "=r"(r2), "=r"(r3) : "r"(a));
}
__device__ __forceinline__ void mma16816(float (&d)[4], const uint32_t (&a)[4],
                                         uint32_t b0, uint32_t b1) {
    asm volatile(
        "mma.sync.aligned.m16n8k16.row.col.f32.f16.f16.f32 "
        "{%0,%1,%2,%3}, {%4,%5,%6,%7}, {%8,%9}, {%0,%1,%2,%3};"
        : "+f"(d[0]), "+f"(d[1]), "+f"(d[2]), "+f"(d[3])
        : "r"(a[0]), "r"(a[1]), "r"(a[2]), "r"(a[3]), "r"(b0), "r"(b1));
}
__device__ __forceinline__ void split2(float v, __half& h, __half& l) {
    h = __float2half(v);
    l = __float2half(v - __half2float(h));
}

// ---------------- scratch ----------------
#define SZ_R1 (HR_DIM * D_DIM)
#define SZ_E1 (HE_DIM * D_DIM)
#define SZ_F1 (HF_DIM * D_DIM)
#define WOFF_R1 0
#define WOFF_M1 (WOFF_R1 + SZ_R1)
#define WOFF_L1 (WOFF_M1 + SZ_E1)
#define WOFF_M2 (WOFF_L1 + SZ_E1)
#define WOFF_L2 (WOFF_M2 + SZ_E1)
#define WOFF_F1 (WOFF_L2 + SZ_E1)
#define WOFF_F2 (WOFF_F1 + SZ_F1)
#define WPOOL_SZ (WOFF_F2 + SZ_F1)

__device__ __align__(256) __half g_whi[WPOOL_SZ];
__device__ __align__(256) __half g_wlo[SZ_R1];      // lo needed only for router weights
__device__ __align__(256) __half g_xhi[B_ROWS * D_DIM];
__device__ __align__(256) __half g_xlo[B_ROWS * D_DIM];
__device__ __align__(256) float g_H[B_ROWS * HR_DIM];
__device__ __align__(256) __half g_xehi[ROWS_PAD * D_DIM];
__device__ __align__(256) __half g_y1hi[(size_t)ROWS_PAD * HE_DIM];
__device__ __align__(256) float g_Ff[B_ROWS * D_DIM];
__device__ __align__(256) __half g_fhi[B_ROWS * D_DIM];
__device__ __align__(256) __half g_ghi[B_ROWS * HF_DIM];
__device__ float g_w[B_ROWS];
__device__ int g_hint[B_ROWS];
__device__ int g_list[2 * B_ROWS];
__device__ int g_cnt[2];
__device__ int g_A0;
__device__ int g_cmap[ROWS_PAD];

__global__ void reset_kernel() {
    if (threadIdx.x < 2) g_cnt[threadIdx.x] = 0;
}
__global__ void calca0_kernel() { g_A0 = ((g_cnt[0] + 127) >> 7) << 7; }

// ---------------- merged weight conversion: [K,N] fp32 -> hi(/lo) fp16 [N,K] --------
__device__ __forceinline__ void wconv_tile(const float* __restrict__ W,
                                           __half* __restrict__ hi, __half* __restrict__ lo,
                                           int K, int N, int bx, int by) {
    __shared__ float t[32][33];
    int k0 = by * 32, n0 = bx * 32;
    int tx = threadIdx.x, ty = threadIdx.y;
#pragma unroll
    for (int j = 0; j < 4; j++)
        t[ty + j * 8][tx] = W[(size_t)(k0 + ty + j * 8) * N + n0 + tx];
    __syncthreads();
#pragma unroll
    for (int j = 0; j < 4; j++) {
        int n = n0 + ty + j * 8, k = k0 + tx;
        __half h, l;
        split2(t[tx][ty + j * 8], h, l);
        hi[(size_t)n * K + k] = h;
        if (lo) lo[(size_t)n * K + k] = l;
    }
}

__global__ void wconv_all_kernel(const float* W_r1, const float* W_m1, const float* W_l1,
                                 const float* W_m2, const float* W_l2,
                                 const float* W_f1, const float* W_f2) {
    __half* hi = g_whi;
    int b = blockIdx.x;
    if (b < 512) { wconv_tile(W_r1, hi + WOFF_R1, g_wlo, D_DIM, HR_DIM, b % 16, b / 16); return; }
    b -= 512;
    if (b < 4096) { wconv_tile(W_m1, hi + WOFF_M1, nullptr, D_DIM, HE_DIM, b % 128, b / 128); return; }
    b -= 4096;
    if (b < 4096) { wconv_tile(W_l1, hi + WOFF_L1, nullptr, D_DIM, HE_DIM, b % 128, b / 128); return; }
    b -= 4096;
    if (b < 4096) { wconv_tile(W_m2, hi + WOFF_M2, nullptr, HE_DIM, D_DIM, b % 32, b / 32); return; }
    b -= 4096;
    if (b < 4096) { wconv_tile(W_l2, hi + WOFF_L2, nullptr, HE_DIM, D_DIM, b % 32, b / 32); return; }
    b -= 4096;
    if (b < 2048) { wconv_tile(W_f1, hi + WOFF_F1, nullptr, D_DIM, HF_DIM, b % 64, b / 64); return; }
    b -= 2048;
    wconv_tile(W_f2, hi + WOFF_F2, nullptr, HF_DIM, D_DIM, b % 32, b / 32);
}
#define WCONV_BLOCKS (512 + 4 * 4096 + 2 * 2048)

__global__ void xconv_kernel(const float* __restrict__ x) {
    size_t i = ((size_t)blockIdx.x * blockDim.x + threadIdx.x) * 4;
    float4 v = *(const float4*)(x + i);
    __half h, l;
    split2(v.x, h, l); g_xhi[i] = h;     g_xlo[i] = l;
    split2(v.y, h, l); g_xhi[i + 1] = h; g_xlo[i + 1] = l;
    split2(v.z, h, l); g_xhi[i + 2] = h; g_xlo[i + 2] = l;
    split2(v.w, h, l); g_xhi[i + 3] = h; g_xlo[i + 3] = l;
}

__global__ void router_head_kernel(const float* __restrict__ Wdom, const float* __restrict__ bdom,
                                   const float* __restrict__ Wmop, const float* __restrict__ Wlt) {
    int warp = (blockIdx.x * blockDim.x + threadIdx.x) >> 5;
    int lane = threadIdx.x & 31;
    if (warp >= B_ROWS) return;
    const float* h = g_H + (size_t)warp * HR_DIM;
    float a0 = 0, a1 = 0, m0 = 0, m1 = 0, m2 = 0, m3 = 0, l0 = 0, l1 = 0, l2 = 0, l3 = 0;
    for (int i = lane; i < HR_DIM; i += 32) {
        float hv = h[i];
        a0 += hv * Wdom[i * 2];     a1 += hv * Wdom[i * 2 + 1];
        m0 += hv * Wmop[i * 4];     m1 += hv * Wmop[i * 4 + 1];
        m2 += hv * Wmop[i * 4 + 2]; m3 += hv * Wmop[i * 4 + 3];
        l0 += hv * Wlt[i * 4];      l1 += hv * Wlt[i * 4 + 1];
        l2 += hv * Wlt[i * 4 + 2];  l3 += hv * Wlt[i * 4 + 3];
    }
#pragma unroll
    for (int o = 16; o > 0; o >>= 1) {
        a0 += __shfl_down_sync(~0u, a0, o); a1 += __shfl_down_sync(~0u, a1, o);
        m0 += __shfl_down_sync(~0u, m0, o); m1 += __shfl_down_sync(~0u, m1, o);
        m2 += __shfl_down_sync(~0u, m2, o); m3 += __shfl_down_sync(~0u, m3, o);
        l0 += __shfl_down_sync(~0u, l0, o); l1 += __shfl_down_sync(~0u, l1, o);
        l2 += __shfl_down_sync(~0u, l2, o); l3 += __shfl_down_sync(~0u, l3, o);
    }
    if (lane == 0) {
        a0 += bdom[0]; a1 += bdom[1];
        int primary = (a1 > a0) ? 1 : 0;
        float w = 1.f / (1.f + expf((primary ? a0 : a1) - (primary ? a1 : a0)));
        int mop = 0; float b = m0;
        if (m1 > b) { b = m1; mop = 1; }
        if (m2 > b) { b = m2; mop = 2; }
        if (m3 > b) { b = m3; mop = 3; }
        int lt = 0; b = l0;
        if (l1 > b) { b = l1; lt = 1; }
        if (l2 > b) { b = l2; lt = 2; }
        if (l3 > b) { b = l3; lt = 3; }
        g_w[warp] = w;
        g_hint[warp] = primary ? lt : mop;
        int pos = atomicAdd(&g_cnt[primary], 1);
        g_list[primary * B_ROWS + pos] = warp;
    }
}

__global__ void gather_kernel(const float* __restrict__ x, const float* __restrict__ op_emb,
                              const float* __restrict__ task_emb) {
    int bidx = blockIdx.x;
    int c0 = g_cnt[0], c1 = g_cnt[1], A0 = g_A0;
    int orig = -1;
    const float* er = nullptr;
    if (bidx < c0) {
        orig = g_list[bidx];
        er = op_emb + (size_t)g_hint[orig] * D_DIM;
    } else if (bidx >= A0 && bidx < A0 + c1) {
        orig = g_list[B_ROWS + bidx - A0];
        er = task_emb + (size_t)g_hint[orig] * D_DIM;
    }
    if (threadIdx.x == 0) g_cmap[bidx] = orig;
    if (orig < 0) return;
    const float* xr = x + (size_t)orig * D_DIM;
    size_t ob = (size_t)bidx * D_DIM;
    for (int i = threadIdx.x * 4; i < D_DIM; i += 512) {
        float4 xv = *(const float4*)(xr + i);
        float4 ev = *(const float4*)(er + i);
        __half2 h01, h23;
        h01.x = __float2half(xv.x + ev.x);
        h01.y = __float2half(xv.y + ev.y);
        h23.x = __float2half(xv.z + ev.z);
        h23.y = __float2half(xv.w + ev.w);
        *(__half2*)(g_xehi + ob + i)     = h01;
        *(__half2*)(g_xehi + ob + i + 2) = h23;
    }
}

// ---------------- HMMA fp16 GEMM: 128x256 tile ----------------
// MODE 0 (router): BK=32, A combined [hi64|lo64] rows, B dual hi/lo, 3 passes (argmax-safe).
// MODE 2 (all other layers): BK=64, A hi only, B single, 1 pass.
template <bool RELU, bool SCAT, bool RESID, bool WF32, bool WBF, bool MERGE, int MODE>
__global__ void __launch_bounds__(512, 1) mm_hmma(
    const __half* __restrict__ Ahi, const __half* __restrict__ Alo,
    const __half* __restrict__ Bhi, const __half* __restrict__ Blo,
    const __half* __restrict__ B2hi,
    const float* __restrict__ bias, const float* __restrict__ bias2,
    float* __restrict__ Cf, __half* __restrict__ Chi,
    const float* __restrict__ resid, int N, int K) {
    constexpr int ABYTES = 16384;
    constexpr int BBYTES = 32768;
    constexpr int STAGE = ABYTES + BBYTES;
    constexpr int NSLOT = 4;
    constexpr int INF = NSLOT - 1;
    constexpr int BKSH = (MODE == 0) ? 5 : 6;

    const int m0 = blockIdx.y * 128;
    if (MERGE) {
        if (m0 >= g_A0 + g_cnt[1]) return;
        if (m0 >= g_A0) { Bhi = B2hi; bias = bias2; }
    }
    const int n0 = blockIdx.x * 256;
    const int tid = threadIdx.x;
    const int lane = tid & 31, wid = tid >> 5;
    const int wm = wid & 3, wn = wid >> 2;  // 4x4 warp grid: warp tile 32x64

    extern __shared__ char sm_raw[];
    char* sm = (char*)(((uintptr_t)sm_raw + 127) & ~(uintptr_t)127);
    const uint32_t sbase = smem_u32(sm);

    float acc[2][8][4];
#pragma unroll
    for (int a = 0; a < 2; a++)
#pragma unroll
        for (int b = 0; b < 8; b++)
#pragma unroll
            for (int c = 0; c < 4; c++) acc[a][b][c] = 0.f;

    const int niter = K >> BKSH;

    auto issue = [&](int it) {
        const int slot = it & 3;
        const int k0 = it << BKSH;
        const uint32_t as = sbase + slot * STAGE;
        const uint32_t bs = as + ABYTES;
        if (MODE == 0) {
            // A combined rows [hi64|lo64]: 1024 cp16
#pragma unroll
            for (int rep = 0; rep < 2; rep++) {
                int c = rep * 512 + tid;
                int r = c >> 3, j8 = c & 7;
                uint32_t loc = (uint32_t)(r * 128 + ((j8 * 16) ^ ((r & 7) << 4)));
                const __half* src =
                    ((j8 >> 2) ? Alo : Ahi) + (size_t)(m0 + r) * K + k0 + (j8 & 3) * 8;
                cp16(as + loc, src);
            }
            // B dual hi/lo: 2048 cp16
#pragma unroll
            for (int rep = 0; rep < 4; rep++) {
                int c = rep * 512 + tid;
                int r = c >> 3, j8 = c & 7;
                uint32_t loc = (uint32_t)(r * 128 + ((j8 * 16) ^ ((r & 7) << 4)));
                const __half* src =
                    ((j8 >> 2) ? Blo : Bhi) + (size_t)(n0 + r) * K + k0 + (j8 & 3) * 8;
                cp16(bs + loc, src);
            }
        } else {
            // A hi only (BK=64): 1024 cp16
#pragma unroll
            for (int rep = 0; rep < 2; rep++) {
                int c = rep * 512 + tid;
                int r = c >> 3, j = c & 7;
                uint32_t loc = (uint32_t)(r * 128 + ((j * 16) ^ ((r & 7) << 4)));
                cp16(as + loc, Ahi + (size_t)(m0 + r) * K + k0 + j * 8);
            }
            // B single (BK=64): 2048 cp16
#pragma unroll
            for (int rep = 0; rep < 4; rep++) {
                int c = rep * 512 + tid;
                int r = c >> 3, j = c & 7;
                uint32_t loc = (uint32_t)(r * 128 + ((j * 16) ^ ((r & 7) << 4)));
                cp16(bs + loc, Bhi + (size_t)(n0 + r) * K + k0 + j * 8);
            }
        }
    };

    auto compute = [&](int slot) {
        const uint32_t as = sbase + slot * STAGE;
        const uint32_t bs = as + ABYTES;
        constexpr int NKS = (MODE == 0) ? 2 : 4;
#pragma unroll
        for (int ks = 0; ks < NKS; ks++) {
            const int kb = ks * 32;
            uint32_t ah[2][4], al[2][4], bq[4][4];
#pragma unroll
            for (int mt = 0; mt < 2; mt++) {
                int r = wm * 32 + mt * 16 + (lane & 15);
                int sw = (r & 7) << 4;
                uint32_t rb = as + r * 128;
                int bo = kb + ((lane >> 4) << 4);
                ldsm4(ah[mt][0], ah[mt][1], ah[mt][2], ah[mt][3], rb + (uint32_t)(bo ^ sw));
                if (MODE == 0)
                    ldsm4(al[mt][0], al[mt][1], al[mt][2], al[mt][3],
                          rb + (uint32_t)((bo + 64) ^ sw));
            }
#pragma unroll
            for (int np = 0; np < 4; np++) {
                int r = wn * 64 + np * 16 + (lane & 7) + ((lane >> 4) << 3);
                int sw = (r & 7) << 4;
                int bo = kb + (((lane >> 3) & 1) << 4);
                ldsm4(bq[np][0], bq[np][1], bq[np][2], bq[np][3],
                      bs + r * 128 + (uint32_t)(bo ^ sw));
            }
            // pass: ah x b
#pragma unroll
            for (int np = 0; np < 4; np++)
#pragma unroll
                for (int mt = 0; mt < 2; mt++) {
                    mma16816(acc[mt][np * 2],     ah[mt], bq[np][0], bq[np][1]);
                    mma16816(acc[mt][np * 2 + 1], ah[mt], bq[np][2], bq[np][3]);
                }
            if (MODE == 0) {
                // pass: al x bh
#pragma unroll
                for (int np = 0; np < 4; np++)
#pragma unroll
                    for (int mt = 0; mt < 2; mt++) {
                        mma16816(acc[mt][np * 2],     al[mt], bq[np][0], bq[np][1]);
                        mma16816(acc[mt][np * 2 + 1], al[mt], bq[np][2], bq[np][3]);
                    }
                // B lo + pass ah x bl
#pragma unroll
                for (int np = 0; np < 4; np++) {
                    int r = wn * 64 + np * 16 + (lane & 7) + ((lane >> 4) << 3);
                    int sw = (r & 7) << 4;
                    int bo = kb + (((lane >> 3) & 1) << 4);
                    ldsm4(bq[np][0], bq[np][1], bq[np][2], bq[np][3],
                          bs + r * 128 + (uint32_t)((bo + 64) ^ sw));
                }
#pragma unroll
                for (int np = 0; np < 4; np++)
#pragma unroll
                    for (int mt = 0; mt < 2; mt++) {
                        mma16816(acc[mt][np * 2],     ah[mt], bq[np][0], bq[np][1]);
                        mma16816(acc[mt][np * 2 + 1], ah[mt], bq[np][2], bq[np][3]);
                    }
            }
        }
    };

#pragma unroll
    for (int p = 0; p < INF; p++) { issue(p); CP_COMMIT; }
    for (int i = 0; i < niter; i++) {
        asm volatile("cp.async.wait_group 2;" ::: "memory");
        __syncthreads();
        if (i + INF < niter) issue(i + INF);
        CP_COMMIT;
        compute(i & 3);
    }

    // ---- epilogue ----
    const int tg = lane & 3, g = lane >> 2;
#pragma unroll
    for (int mt = 0; mt < 2; mt++) {
#pragma unroll
        for (int h2 = 0; h2 < 2; h2++) {
            int row = m0 + wm * 32 + mt * 16 + g + h2 * 8;
            int orig = row;
            float wsc = 1.f;
            bool valid = true;
            if (SCAT) {
                orig = g_cmap[row];
                valid = orig >= 0;
                wsc = valid ? g_w[orig] : 0.f;
            }
            if (!valid) continue;
            size_t rowoff = (size_t)orig * N;
#pragma unroll
            for (int nt = 0; nt < 8; nt++) {
                int col = n0 + wn * 64 + nt * 8 + tg * 2;
                float v0 = acc[mt][nt][h2 * 2]     + bias[col];
                float v1 = acc[mt][nt][h2 * 2 + 1] + bias[col + 1];
                if (RELU) { v0 = fmaxf(v0, 0.f); v1 = fmaxf(v1, 0.f); }
                if (SCAT) { v0 *= wsc; v1 *= wsc; }
                if (RESID) {
                    float2 rv = *(const float2*)(resid + rowoff + col);
                    v0 += rv.x; v1 += rv.y;
                }
                if (WF32) {
                    float2 o; o.x = v0; o.y = v1;
                    *(float2*)(Cf + rowoff + col) = o;
                }
                if (WBF) {
                    __half2 hh;
                    hh.x = __float2half(v0);
                    hh.y = __float2half(v1);
                    *(__half2*)(Chi + rowoff + col) = hh;
                }
            }
        }
    }
}

#define DYN_SMEM (4 * 49152 + 128)

// ---------------- launch ----------------
extern "C" void kernel_launch(void* const* d_in, const int* in_sizes, int n_in,
                              void* d_out, int out_size) {
    const float* x        = (const float*)d_in[0];
    const float* W_r1     = (const float*)d_in[1];
    const float* b_r1     = (const float*)d_in[2];
    const float* W_dom    = (const float*)d_in[3];
    const float* b_dom    = (const float*)d_in[4];
    const float* W_mop    = (const float*)d_in[5];
    const float* W_lt     = (const float*)d_in[6];
    const float* op_emb   = (const float*)d_in[7];
    const float* W_m1     = (const float*)d_in[8];
    const float* b_m1     = (const float*)d_in[9];
    const float* W_m2     = (const float*)d_in[10];
    const float* b_m2     = (const float*)d_in[11];
    const float* task_emb = (const float*)d_in[12];
    const float* W_l1     = (const float*)d_in[13];
    const float* b_l1     = (const float*)d_in[14];
    const float* W_l2     = (const float*)d_in[15];
    const float* b_l2     = (const float*)d_in[16];
    const float* W_f1     = (const float*)d_in[17];
    const float* b_f1     = (const float*)d_in[18];
    const float* W_f2     = (const float*)d_in[19];
    const float* b_f2     = (const float*)d_in[20];
    float* out = (float*)d_out;

    __half *whi, *wlo, *xhi, *xlo, *xehi, *y1hi, *fhi, *ghi;
    float *H, *Ff;
    cudaGetSymbolAddress((void**)&whi, g_whi);
    cudaGetSymbolAddress((void**)&wlo, g_wlo);
    cudaGetSymbolAddress((void**)&xhi, g_xhi);
    cudaGetSymbolAddress((void**)&xlo, g_xlo);
    cudaGetSymbolAddress((void**)&xehi, g_xehi);
    cudaGetSymbolAddress((void**)&y1hi, g_y1hi);
    cudaGetSymbolAddress((void**)&fhi, g_fhi);
    cudaGetSymbolAddress((void**)&ghi, g_ghi);
    cudaGetSymbolAddress((void**)&H, g_H);
    cudaGetSymbolAddress((void**)&Ff, g_Ff);

    cudaFuncSetAttribute(
        (const void*)mm_hmma<true, false, false, true, false, false, 0>,
        cudaFuncAttributeMaxDynamicSharedMemorySize, DYN_SMEM);
    cudaFuncSetAttribute(
        (const void*)mm_hmma<true, false, false, false, true, true, 2>,
        cudaFuncAttributeMaxDynamicSharedMemorySize, DYN_SMEM);
    cudaFuncSetAttribute(
        (const void*)mm_hmma<false, true, false, true, true, true, 2>,
        cudaFuncAttributeMaxDynamicSharedMemorySize, DYN_SMEM);
    cudaFuncSetAttribute(
        (const void*)mm_hmma<true, false, false, false, true, false, 2>,
        cudaFuncAttributeMaxDynamicSharedMemorySize, DYN_SMEM);
    cudaFuncSetAttribute(
        (const void*)mm_hmma<false, false, true, true, false, false, 2>,
        cudaFuncAttributeMaxDynamicSharedMemorySize, DYN_SMEM);

    dim3 blk(512);
    int mtiles = B_ROWS / 128;
    int mtiles_pad = ROWS_PAD / 128;

    reset_kernel<<<1, 32>>>();
    wconv_all_kernel<<<WCONV_BLOCKS, dim3(32, 8)>>>(W_r1, W_m1, W_l1, W_m2, W_l2, W_f1, W_f2);
    xconv_kernel<<<B_ROWS * D_DIM / 1024, 256>>>(x);

    // router (MODE0, fp16x3 — argmax-safe): H = relu(x @ W_r1 + b_r1)
    mm_hmma<true, false, false, true, false, false, 0>
        <<<dim3(HR_DIM / 256, mtiles), blk, DYN_SMEM>>>(
        xhi, xlo, whi + WOFF_R1, wlo, nullptr, b_r1, nullptr,
        H, nullptr, nullptr, HR_DIM, D_DIM);
    router_head_kernel<<<B_ROWS / 8, 256>>>(W_dom, b_dom, W_mop, W_lt);
    calca0_kernel<<<1, 1>>>();
    gather_kernel<<<ROWS_PAD, 128>>>(x, op_emb, task_emb);

    // expert layer 1 (MODE2 merged, 1 pass): Y1 = relu(XE @ W1 + b1)
    mm_hmma<true, false, false, false, true, true, 2>
        <<<dim3(HE_DIM / 256, mtiles_pad), blk, DYN_SMEM>>>(
        xehi, nullptr, whi + WOFF_M1, nullptr, whi + WOFF_L1, b_m1, b_l1,
        nullptr, y1hi, nullptr, HE_DIM, D_DIM);
    // expert layer 2 (MODE2 merged, scatter): FUSED = w*(Y1 @ W2 + b2)
    mm_hmma<false, true, false, true, true, true, 2>
        <<<dim3(D_DIM / 256, mtiles_pad), blk, DYN_SMEM>>>(
        y1hi, nullptr, whi + WOFF_M2, nullptr, whi + WOFF_L2, b_m2, b_l2,
        Ff, fhi, nullptr, D_DIM, HE_DIM);
    // fusion layer 1 (MODE2): G = relu(FUSED @ W_f1 + b_f1)
    mm_hmma<true, false, false, false, true, false, 2>
        <<<dim3(HF_DIM / 256, mtiles), blk, DYN_SMEM>>>(
        fhi, nullptr, whi + WOFF_F1, nullptr, nullptr, b_f1, nullptr,
        nullptr, ghi, nullptr, HF_DIM, D_DIM);
    // fusion layer 2 (MODE2): out = FUSED + G @ W_f2 + b_f2
    mm_hmma<false, false, true, true, false, false, 2>
        <<<dim3(D_DIM / 256, mtiles), blk, DYN_SMEM>>>(
        ghi, nullptr, whi + WOFF_F2, nullptr, nullptr, b_f2, nullptr,
        out, nullptr, Ff, D_DIM, HF_DIM);
}

// round 14
// speedup vs baseline: 1.5155x; 1.5155x over previous
#include <cuda_runtime.h>
#include <cuda_fp16.h>
#include <stdint.h>
#include <math.h>

#define B_ROWS 8192
#define ROWS_PAD 8448
#define D_DIM 1024
#define HR_DIM 512
#define HE_DIM 4096
#define HF_DIM 2048

// ---------------- PTX helpers (base sm_103-safe) ----------------
__device__ __forceinline__ uint32_t smem_u32(const void* p) {
    uint32_t a;
    asm("{ .reg .u64 t; cvta.to.shared.u64 t, %1; cvt.u32.u64 %0, t; }" : "=r"(a) : "l"(p));
    return a;
}
__device__ __forceinline__ void cp16(uint32_t dst, const void* src) {
    asm volatile("cp.async.cg.shared.global [%0], [%1], 16;" :: "r"(dst), "l"(src));
}
#define CP_COMMIT asm volatile("cp.async.commit_group;" ::: "memory")

__device__ __forceinline__ void ldsm4(uint32_t& r0, uint32_t& r1, uint32_t& r2, uint32_t& r3,
                                      uint32_t a) {
    asm volatile("ldmatrix.sync.aligned.m8n8.x4.shared.b16 {%0,%1,%2,%3}, [%4];"
                 : "=r"(r0), "=r"(r1), "=r"(r2), "=r"(r3) : "r"(a));
}
__device__ __forceinline__ void mma16816(float (&d)[4], const uint32_t (&a)[4],
                                         uint32_t b0, uint32_t b1) {
    asm volatile(
        "mma.sync.aligned.m16n8k16.row.col.f32.f16.f16.f32 "
        "{%0,%1,%2,%3}, {%4,%5,%6,%7}, {%8,%9}, {%0,%1,%2,%3};"
        : "+f"(d[0]), "+f"(d[1]), "+f"(d[2]), "+f"(d[3])
        : "r"(a[0]), "r"(a[1]), "r"(a[2]), "r"(a[3]), "r"(b0), "r"(b1));
}
__device__ __forceinline__ void split2(float v, __half& h, __half& l) {
    h = __float2half(v);
    l = __float2half(v - __half2float(h));
}

// ---------------- scratch ----------------
#define SZ_R1 (HR_DIM * D_DIM)
#define SZ_E1 (HE_DIM * D_DIM)
#define SZ_F1 (HF_DIM * D_DIM)
#define WOFF_R1 0
#define WOFF_M1 (WOFF_R1 + SZ_R1)
#define WOFF_L1 (WOFF_M1 + SZ_E1)
#define WOFF_M2 (WOFF_L1 + SZ_E1)
#define WOFF_L2 (WOFF_M2 + SZ_E1)
#define WOFF_F1 (WOFF_L2 + SZ_E1)
#define WOFF_F2 (WOFF_F1 + SZ_F1)
#define WPOOL_SZ (WOFF_F2 + SZ_F1)

__device__ __align__(256) __half g_whi[WPOOL_SZ];
__device__ __align__(256) __half g_wlo[SZ_R1];      // lo only for router weights
__device__ __align__(256) __half g_xhi[B_ROWS * D_DIM];
__device__ __align__(256) __half g_xlo[B_ROWS * D_DIM];
__device__ __align__(256) float g_H[B_ROWS * HR_DIM];
__device__ __align__(256) __half g_xehi[ROWS_PAD * D_DIM];
__device__ __align__(256) __half g_y1hi[(size_t)ROWS_PAD * HE_DIM];
__device__ __align__(256) float g_Ff[B_ROWS * D_DIM];
__device__ __align__(256) __half g_fhi[B_ROWS * D_DIM];
__device__ __align__(256) __half g_ghi[B_ROWS * HF_DIM];
__device__ float g_w[B_ROWS];
__device__ int g_hint[B_ROWS];
__device__ int g_list[2 * B_ROWS];
__device__ int g_cnt[2];
__device__ int g_A0;
__device__ int g_cmap[ROWS_PAD];

__global__ void reset_kernel() {
    if (threadIdx.x < 2) g_cnt[threadIdx.x] = 0;
}
__global__ void calca0_kernel() { g_A0 = ((g_cnt[0] + 127) >> 7) << 7; }

// ---------------- merged weight conversion: [K,N] fp32 -> hi(/lo) fp16 [N,K] --------
__device__ __forceinline__ void wconv_tile(const float* __restrict__ W,
                                           __half* __restrict__ hi, __half* __restrict__ lo,
                                           int K, int N, int bx, int by) {
    __shared__ float t[32][33];
    int k0 = by * 32, n0 = bx * 32;
    int tx = threadIdx.x, ty = threadIdx.y;
#pragma unroll
    for (int j = 0; j < 4; j++)
        t[ty + j * 8][tx] = W[(size_t)(k0 + ty + j * 8) * N + n0 + tx];
    __syncthreads();
#pragma unroll
    for (int j = 0; j < 4; j++) {
        int n = n0 + ty + j * 8, k = k0 + tx;
        __half h, l;
        split2(t[tx][ty + j * 8], h, l);
        hi[(size_t)n * K + k] = h;
        if (lo) lo[(size_t)n * K + k] = l;
    }
}

__global__ void wconv_all_kernel(const float* W_r1, const float* W_m1, const float* W_l1,
                                 const float* W_m2, const float* W_l2,
                                 const float* W_f1, const float* W_f2) {
    __half* hi = g_whi;
    int b = blockIdx.x;
    if (b < 512) { wconv_tile(W_r1, hi + WOFF_R1, g_wlo, D_DIM, HR_DIM, b % 16, b / 16); return; }
    b -= 512;
    if (b < 4096) { wconv_tile(W_m1, hi + WOFF_M1, nullptr, D_DIM, HE_DIM, b % 128, b / 128); return; }
    b -= 4096;
    if (b < 4096) { wconv_tile(W_l1, hi + WOFF_L1, nullptr, D_DIM, HE_DIM, b % 128, b / 128); return; }
    b -= 4096;
    if (b < 4096) { wconv_tile(W_m2, hi + WOFF_M2, nullptr, HE_DIM, D_DIM, b % 32, b / 32); return; }
    b -= 4096;
    if (b < 4096) { wconv_tile(W_l2, hi + WOFF_L2, nullptr, HE_DIM, D_DIM, b % 32, b / 32); return; }
    b -= 4096;
    if (b < 2048) { wconv_tile(W_f1, hi + WOFF_F1, nullptr, D_DIM, HF_DIM, b % 64, b / 64); return; }
    b -= 2048;
    wconv_tile(W_f2, hi + WOFF_F2, nullptr, HF_DIM, D_DIM, b % 32, b / 32);
}
#define WCONV_BLOCKS (512 + 4 * 4096 + 2 * 2048)

__global__ void xconv_kernel(const float* __restrict__ x) {
    size_t i = ((size_t)blockIdx.x * blockDim.x + threadIdx.x) * 4;
    float4 v = *(const float4*)(x + i);
    __half h, l;
    split2(v.x, h, l); g_xhi[i] = h;     g_xlo[i] = l;
    split2(v.y, h, l); g_xhi[i + 1] = h; g_xlo[i + 1] = l;
    split2(v.z, h, l); g_xhi[i + 2] = h; g_xlo[i + 2] = l;
    split2(v.w, h, l); g_xhi[i + 3] = h; g_xlo[i + 3] = l;
}

__global__ void router_head_kernel(const float* __restrict__ Wdom, const float* __restrict__ bdom,
                                   const float* __restrict__ Wmop, const float* __restrict__ Wlt) {
    int warp = (blockIdx.x * blockDim.x + threadIdx.x) >> 5;
    int lane = threadIdx.x & 31;
    if (warp >= B_ROWS) return;
    const float* h = g_H + (size_t)warp * HR_DIM;
    float a0 = 0, a1 = 0, m0 = 0, m1 = 0, m2 = 0, m3 = 0, l0 = 0, l1 = 0, l2 = 0, l3 = 0;
    for (int i = lane; i < HR_DIM; i += 32) {
        float hv = h[i];
        a0 += hv * Wdom[i * 2];     a1 += hv * Wdom[i * 2 + 1];
        m0 += hv * Wmop[i * 4];     m1 += hv * Wmop[i * 4 + 1];
        m2 += hv * Wmop[i * 4 + 2]; m3 += hv * Wmop[i * 4 + 3];
        l0 += hv * Wlt[i * 4];      l1 += hv * Wlt[i * 4 + 1];
        l2 += hv * Wlt[i * 4 + 2];  l3 += hv * Wlt[i * 4 + 3];
    }
#pragma unroll
    for (int o = 16; o > 0; o >>= 1) {
        a0 += __shfl_down_sync(~0u, a0, o); a1 += __shfl_down_sync(~0u, a1, o);
        m0 += __shfl_down_sync(~0u, m0, o); m1 += __shfl_down_sync(~0u, m1, o);
        m2 += __shfl_down_sync(~0u, m2, o); m3 += __shfl_down_sync(~0u, m3, o);
        l0 += __shfl_down_sync(~0u, l0, o); l1 += __shfl_down_sync(~0u, l1, o);
        l2 += __shfl_down_sync(~0u, l2, o); l3 += __shfl_down_sync(~0u, l3, o);
    }
    if (lane == 0) {
        a0 += bdom[0]; a1 += bdom[1];
        int primary = (a1 > a0) ? 1 : 0;
        float w = 1.f / (1.f + expf((primary ? a0 : a1) - (primary ? a1 : a0)));
        int mop = 0; float b = m0;
        if (m1 > b) { b = m1; mop = 1; }
        if (m2 > b) { b = m2; mop = 2; }
        if (m3 > b) { b = m3; mop = 3; }
        int lt = 0; b = l0;
        if (l1 > b) { b = l1; lt = 1; }
        if (l2 > b) { b = l2; lt = 2; }
        if (l3 > b) { b = l3; lt = 3; }
        g_w[warp] = w;
        g_hint[warp] = primary ? lt : mop;
        int pos = atomicAdd(&g_cnt[primary], 1);
        g_list[primary * B_ROWS + pos] = warp;
    }
}

__global__ void gather_kernel(const float* __restrict__ x, const float* __restrict__ op_emb,
                              const float* __restrict__ task_emb) {
    int bidx = blockIdx.x;
    int c0 = g_cnt[0], c1 = g_cnt[1], A0 = g_A0;
    int orig = -1;
    const float* er = nullptr;
    if (bidx < c0) {
        orig = g_list[bidx];
        er = op_emb + (size_t)g_hint[orig] * D_DIM;
    } else if (bidx >= A0 && bidx < A0 + c1) {
        orig = g_list[B_ROWS + bidx - A0];
        er = task_emb + (size_t)g_hint[orig] * D_DIM;
    }
    if (threadIdx.x == 0) g_cmap[bidx] = orig;
    if (orig < 0) return;
    const float* xr = x + (size_t)orig * D_DIM;
    size_t ob = (size_t)bidx * D_DIM;
    for (int i = threadIdx.x * 4; i < D_DIM; i += 512) {
        float4 xv = *(const float4*)(xr + i);
        float4 ev = *(const float4*)(er + i);
        __half2 h01, h23;
        h01.x = __float2half(xv.x + ev.x);
        h01.y = __float2half(xv.y + ev.y);
        h23.x = __float2half(xv.z + ev.z);
        h23.y = __float2half(xv.w + ev.w);
        *(__half2*)(g_xehi + ob + i)     = h01;
        *(__half2*)(g_xehi + ob + i + 2) = h23;
    }
}

// ---------------- HMMA fp16 GEMM: 128x256 tile ----------------
// MODE 0 (router): BK=32, 128B rows [hi64|lo64] for A, dual-B, 3 passes, 4 slots (argmax-safe).
// MODE 2 (others): BK=128, 256B rows, A hi only, B single, 1 pass, 2 slots, 128 MMAs/iter.
template <bool RELU, bool SCAT, bool RESID, bool WF32, bool WBF, bool MERGE, int MODE>
__global__ void __launch_bounds__(512, 1) mm_hmma(
    const __half* __restrict__ Ahi, const __half* __restrict__ Alo,
    const __half* __restrict__ Bhi, const __half* __restrict__ Blo,
    const __half* __restrict__ B2hi,
    const float* __restrict__ bias, const float* __restrict__ bias2,
    float* __restrict__ Cf, __half* __restrict__ Chi,
    const float* __restrict__ resid, int N, int K) {
    constexpr int ROWB   = (MODE == 0) ? 128 : 256;
    constexpr int ABYTES = 128 * ROWB;
    constexpr int BBYTES = 256 * ROWB;
    constexpr int STAGE  = ABYTES + BBYTES;
    constexpr int BKSH   = (MODE == 0) ? 5 : 7;
    constexpr int NKS    = (MODE == 0) ? 2 : 8;

    const int m0 = blockIdx.y * 128;
    if (MERGE) {
        if (m0 >= g_A0 + g_cnt[1]) return;
        if (m0 >= g_A0) { Bhi = B2hi; bias = bias2; }
    }
    const int n0 = blockIdx.x * 256;
    const int tid = threadIdx.x;
    const int lane = tid & 31, wid = tid >> 5;
    const int wm = wid & 3, wn = wid >> 2;  // 4x4 warp grid: warp tile 32x64

    extern __shared__ char sm_raw[];
    char* sm = (char*)(((uintptr_t)sm_raw + 127) & ~(uintptr_t)127);
    const uint32_t sbase = smem_u32(sm);

    float acc[2][8][4];
#pragma unroll
    for (int a = 0; a < 2; a++)
#pragma unroll
        for (int b = 0; b < 8; b++)
#pragma unroll
            for (int c = 0; c < 4; c++) acc[a][b][c] = 0.f;

    const int niter = K >> BKSH;

    auto issue = [&](int it) {
        const int slot = (MODE == 0) ? (it & 3) : (it & 1);
        const int k0 = it << BKSH;
        const uint32_t as = sbase + slot * STAGE;
        const uint32_t bs = as + ABYTES;
        if (MODE == 0) {
            // A combined rows [hi64|lo64]: 1024 cp16
#pragma unroll
            for (int rep = 0; rep < 2; rep++) {
                int c = rep * 512 + tid;
                int r = c >> 3, j8 = c & 7;
                uint32_t loc = (uint32_t)(r * 128 + ((j8 * 16) ^ ((r & 7) << 4)));
                const __half* src =
                    ((j8 >> 2) ? Alo : Ahi) + (size_t)(m0 + r) * K + k0 + (j8 & 3) * 8;
                cp16(as + loc, src);
            }
            // B dual hi/lo: 2048 cp16
#pragma unroll
            for (int rep = 0; rep < 4; rep++) {
                int c = rep * 512 + tid;
                int r = c >> 3, j8 = c & 7;
                uint32_t loc = (uint32_t)(r * 128 + ((j8 * 16) ^ ((r & 7) << 4)));
                const __half* src =
                    ((j8 >> 2) ? Blo : Bhi) + (size_t)(n0 + r) * K + k0 + (j8 & 3) * 8;
                cp16(bs + loc, src);
            }
        } else {
            // A hi only, 256B rows: 2048 cp16
#pragma unroll
            for (int rep = 0; rep < 4; rep++) {
                int c = rep * 512 + tid;
                int r = c >> 4, j = c & 15;
                uint32_t loc = (uint32_t)(r * 256 + ((j * 16) ^ ((r & 7) << 4)));
                cp16(as + loc, Ahi + (size_t)(m0 + r) * K + k0 + j * 8);
            }
            // B single, 256B rows: 4096 cp16
#pragma unroll
            for (int rep = 0; rep < 8; rep++) {
                int c = rep * 512 + tid;
                int r = c >> 4, j = c & 15;
                uint32_t loc = (uint32_t)(r * 256 + ((j * 16) ^ ((r & 7) << 4)));
                cp16(bs + loc, Bhi + (size_t)(n0 + r) * K + k0 + j * 8);
            }
        }
    };

    auto compute = [&](int slot) {
        const uint32_t as = sbase + slot * STAGE;
        const uint32_t bs = as + ABYTES;
#pragma unroll
        for (int ks = 0; ks < NKS; ks++) {
            const int kb = ks * 32;
            uint32_t ah[2][4], al[2][4], bq[4][4];
#pragma unroll
            for (int mt = 0; mt < 2; mt++) {
                int r = wm * 32 + mt * 16 + (lane & 15);
                int sw = (r & 7) << 4;
                uint32_t rb = as + r * ROWB;
                int bo = kb + ((lane >> 4) << 4);
                ldsm4(ah[mt][0], ah[mt][1], ah[mt][2], ah[mt][3], rb + (uint32_t)(bo ^ sw));
                if (MODE == 0)
                    ldsm4(al[mt][0], al[mt][1], al[mt][2], al[mt][3],
                          rb + (uint32_t)((bo + 64) ^ sw));
            }
#pragma unroll
            for (int np = 0; np < 4; np++) {
                int r = wn * 64 + np * 16 + (lane & 7) + ((lane >> 4) << 3);
                int sw = (r & 7) << 4;
                int bo = kb + (((lane >> 3) & 1) << 4);
                ldsm4(bq[np][0], bq[np][1], bq[np][2], bq[np][3],
                      bs + r * ROWB + (uint32_t)(bo ^ sw));
            }
            // pass: ah x b
#pragma unroll
            for (int np = 0; np < 4; np++)
#pragma unroll
                for (int mt = 0; mt < 2; mt++) {
                    mma16816(acc[mt][np * 2],     ah[mt], bq[np][0], bq[np][1]);
                    mma16816(acc[mt][np * 2 + 1], ah[mt], bq[np][2], bq[np][3]);
                }
            if (MODE == 0) {
                // pass: al x bh
#pragma unroll
                for (int np = 0; np < 4; np++)
#pragma unroll
                    for (int mt = 0; mt < 2; mt++) {
                        mma16816(acc[mt][np * 2],     al[mt], bq[np][0], bq[np][1]);
                        mma16816(acc[mt][np * 2 + 1], al[mt], bq[np][2], bq[np][3]);
                    }
                // B lo + pass ah x bl
#pragma unroll
                for (int np = 0; np < 4; np++) {
                    int r = wn * 64 + np * 16 + (lane & 7) + ((lane >> 4) << 3);
                    int sw = (r & 7) << 4;
                    int bo = kb + (((lane >> 3) & 1) << 4);
                    ldsm4(bq[np][0], bq[np][1], bq[np][2], bq[np][3],
                          bs + r * 128 + (uint32_t)((bo + 64) ^ sw));
                }
#pragma unroll
                for (int np = 0; np < 4; np++)
#pragma unroll
                    for (int mt = 0; mt < 2; mt++) {
                        mma16816(acc[mt][np * 2],     ah[mt], bq[np][0], bq[np][1]);
                        mma16816(acc[mt][np * 2 + 1], ah[mt], bq[np][2], bq[np][3]);
                    }
            }
        }
    };

    if (MODE == 0) {
        issue(0); CP_COMMIT;
        issue(1); CP_COMMIT;
        issue(2); CP_COMMIT;
        for (int i = 0; i < niter; i++) {
            asm volatile("cp.async.wait_group 2;" ::: "memory");
            __syncthreads();
            if (i + 3 < niter) issue(i + 3);
            CP_COMMIT;
            compute(i & 3);
        }
    } else {
        // 2-slot: copy of i+1 overlaps compute(i); sync at iteration end frees the slot.
        issue(0); CP_COMMIT;
        asm volatile("cp.async.wait_group 0;" ::: "memory");
        __syncthreads();
        for (int i = 0; i < niter; i++) {
            if (i + 1 < niter) { issue(i + 1); CP_COMMIT; }
            compute(i & 1);
            if (i + 1 < niter) {
                asm volatile("cp.async.wait_group 0;" ::: "memory");
            }
            __syncthreads();
        }
    }

    // ---- epilogue ----
    const int tg = lane & 3, g = lane >> 2;
#pragma unroll
    for (int mt = 0; mt < 2; mt++) {
#pragma unroll
        for (int h2 = 0; h2 < 2; h2++) {
            int row = m0 + wm * 32 + mt * 16 + g + h2 * 8;
            int orig = row;
            float wsc = 1.f;
            bool valid = true;
            if (SCAT) {
                orig = g_cmap[row];
                valid = orig >= 0;
                wsc = valid ? g_w[orig] : 0.f;
            }
            if (!valid) continue;
            size_t rowoff = (size_t)orig * N;
#pragma unroll
            for (int nt = 0; nt < 8; nt++) {
                int col = n0 + wn * 64 + nt * 8 + tg * 2;
                float v0 = acc[mt][nt][h2 * 2]     + bias[col];
                float v1 = acc[mt][nt][h2 * 2 + 1] + bias[col + 1];
                if (RELU) { v0 = fmaxf(v0, 0.f); v1 = fmaxf(v1, 0.f); }
                if (SCAT) { v0 *= wsc; v1 *= wsc; }
                if (RESID) {
                    float2 rv = *(const float2*)(resid + rowoff + col);
                    v0 += rv.x; v1 += rv.y;
                }
                if (WF32) {
                    float2 o; o.x = v0; o.y = v1;
                    *(float2*)(Cf + rowoff + col) = o;
                }
                if (WBF) {
                    __half2 hh;
                    hh.x = __float2half(v0);
                    hh.y = __float2half(v1);
                    *(__half2*)(Chi + rowoff + col) = hh;
                }
            }
        }
    }
}

#define DYN0 (4 * 49152 + 128)
#define DYN2 (2 * 98304 + 128)

// ---------------- launch ----------------
extern "C" void kernel_launch(void* const* d_in, const int* in_sizes, int n_in,
                              void* d_out, int out_size) {
    const float* x        = (const float*)d_in[0];
    const float* W_r1     = (const float*)d_in[1];
    const float* b_r1     = (const float*)d_in[2];
    const float* W_dom    = (const float*)d_in[3];
    const float* b_dom    = (const float*)d_in[4];
    const float* W_mop    = (const float*)d_in[5];
    const float* W_lt     = (const float*)d_in[6];
    const float* op_emb   = (const float*)d_in[7];
    const float* W_m1     = (const float*)d_in[8];
    const float* b_m1     = (const float*)d_in[9];
    const float* W_m2     = (const float*)d_in[10];
    const float* b_m2     = (const float*)d_in[11];
    const float* task_emb = (const float*)d_in[12];
    const float* W_l1     = (const float*)d_in[13];
    const float* b_l1     = (const float*)d_in[14];
    const float* W_l2     = (const float*)d_in[15];
    const float* b_l2     = (const float*)d_in[16];
    const float* W_f1     = (const float*)d_in[17];
    const float* b_f1     = (const float*)d_in[18];
    const float* W_f2     = (const float*)d_in[19];
    const float* b_f2     = (const float*)d_in[20];
    float* out = (float*)d_out;

    __half *whi, *wlo, *xhi, *xlo, *xehi, *y1hi, *fhi, *ghi;
    float *H, *Ff;
    cudaGetSymbolAddress((void**)&whi, g_whi);
    cudaGetSymbolAddress((void**)&wlo, g_wlo);
    cudaGetSymbolAddress((void**)&xhi, g_xhi);
    cudaGetSymbolAddress((void**)&xlo, g_xlo);
    cudaGetSymbolAddress((void**)&xehi, g_xehi);
    cudaGetSymbolAddress((void**)&y1hi, g_y1hi);
    cudaGetSymbolAddress((void**)&fhi, g_fhi);
    cudaGetSymbolAddress((void**)&ghi, g_ghi);
    cudaGetSymbolAddress((void**)&H, g_H);
    cudaGetSymbolAddress((void**)&Ff, g_Ff);

    cudaFuncSetAttribute(
        (const void*)mm_hmma<true, false, false, true, false, false, 0>,
        cudaFuncAttributeMaxDynamicSharedMemorySize, DYN0);
    cudaFuncSetAttribute(
        (const void*)mm_hmma<true, false, false, false, true, true, 2>,
        cudaFuncAttributeMaxDynamicSharedMemorySize, DYN2);
    cudaFuncSetAttribute(
        (const void*)mm_hmma<false, true, false, true, true, true, 2>,
        cudaFuncAttributeMaxDynamicSharedMemorySize, DYN2);
    cudaFuncSetAttribute(
        (const void*)mm_hmma<true, false, false, false, true, false, 2>,
        cudaFuncAttributeMaxDynamicSharedMemorySize, DYN2);
    cudaFuncSetAttribute(
        (const void*)mm_hmma<false, false, true, true, false, false, 2>,
        cudaFuncAttributeMaxDynamicSharedMemorySize, DYN2);

    dim3 blk(512);
    int mtiles = B_ROWS / 128;
    int mtiles_pad = ROWS_PAD / 128;

    reset_kernel<<<1, 32>>>();
    wconv_all_kernel<<<WCONV_BLOCKS, dim3(32, 8)>>>(W_r1, W_m1, W_l1, W_m2, W_l2, W_f1, W_f2);
    xconv_kernel<<<B_ROWS * D_DIM / 1024, 256>>>(x);

    // router (MODE0, fp16x3 — argmax-safe): H = relu(x @ W_r1 + b_r1)
    mm_hmma<true, false, false, true, false, false, 0>
        <<<dim3(HR_DIM / 256, mtiles), blk, DYN0>>>(
        xhi, xlo, whi + WOFF_R1, wlo, nullptr, b_r1, nullptr,
        H, nullptr, nullptr, HR_DIM, D_DIM);
    router_head_kernel<<<B_ROWS / 8, 256>>>(W_dom, b_dom, W_mop, W_lt);
    calca0_kernel<<<1, 1>>>();
    gather_kernel<<<ROWS_PAD, 128>>>(x, op_emb, task_emb);

    // expert layer 1 (MODE2 merged, BK=128): Y1 = relu(XE @ W1 + b1)
    mm_hmma<true, false, false, false, true, true, 2>
        <<<dim3(HE_DIM / 256, mtiles_pad), blk, DYN2>>>(
        xehi, nullptr, whi + WOFF_M1, nullptr, whi + WOFF_L1, b_m1, b_l1,
        nullptr, y1hi, nullptr, HE_DIM, D_DIM);
    // expert layer 2 (MODE2 merged, scatter, BK=128): FUSED = w*(Y1 @ W2 + b2)
    mm_hmma<false, true, false, true, true, true, 2>
        <<<dim3(D_DIM / 256, mtiles_pad), blk, DYN2>>>(
        y1hi, nullptr, whi + WOFF_M2, nullptr, whi + WOFF_L2, b_m2, b_l2,
        Ff, fhi, nullptr, D_DIM, HE_DIM);
    // fusion layer 1 (MODE2, BK=128): G = relu(FUSED @ W_f1 + b_f1)
    mm_hmma<true, false, false, false, true, false, 2>
        <<<dim3(HF_DIM / 256, mtiles), blk, DYN2>>>(
        fhi, nullptr, whi + WOFF_F1, nullptr, nullptr, b_f1, nullptr,
        nullptr, ghi, nullptr, HF_DIM, D_DIM);
    // fusion layer 2 (MODE2, BK=128): out = FUSED + G @ W_f2 + b_f2
    mm_hmma<false, false, true, true, false, false, 2>
        <<<dim3(D_DIM / 256, mtiles), blk, DYN2>>>(
        ghi, nullptr, whi + WOFF_F2, nullptr, nullptr, b_f2, nullptr,
        out, nullptr, Ff, D_DIM, HF_DIM);
}

// round 17
// speedup vs baseline: 1.5367x; 1.0140x over previous
#include <cuda_runtime.h>
#include <cuda_fp16.h>
#include <stdint.h>
#include <math.h>

#define B_ROWS 8192
#define ROWS_PAD 8448
#define D_DIM 1024
#define HR_DIM 512
#define HE_DIM 4096
#define HF_DIM 2048

// ---------------- PTX helpers (base sm_103-safe) ----------------
__device__ __forceinline__ uint32_t smem_u32(const void* p) {
    uint32_t a;
    asm("{ .reg .u64 t; cvta.to.shared.u64 t, %1; cvt.u32.u64 %0, t; }" : "=r"(a) : "l"(p));
    return a;
}
__device__ __forceinline__ void cp16(uint32_t dst, const void* src) {
    asm volatile("cp.async.cg.shared.global [%0], [%1], 16;" :: "r"(dst), "l"(src));
}
#define CP_COMMIT asm volatile("cp.async.commit_group;" ::: "memory")
#define CP_WAIT0  asm volatile("cp.async.wait_group 0;" ::: "memory")

__device__ __forceinline__ void ldsm4(uint32_t& r0, uint32_t& r1, uint32_t& r2, uint32_t& r3,
                                      uint32_t a) {
    asm volatile("ldmatrix.sync.aligned.m8n8.x4.shared.b16 {%0,%1,%2,%3}, [%4];"
                 : "=r"(r0), "=r"(r1), "=r"(r2), "=r"(r3) : "r"(a));
}
__device__ __forceinline__ void mma16816(float (&d)[4], const uint32_t (&a)[4],
                                         uint32_t b0, uint32_t b1) {
    asm volatile(
        "mma.sync.aligned.m16n8k16.row.col.f32.f16.f16.f32 "
        "{%0,%1,%2,%3}, {%4,%5,%6,%7}, {%8,%9}, {%0,%1,%2,%3};"
        : "+f"(d[0]), "+f"(d[1]), "+f"(d[2]), "+f"(d[3])
        : "r"(a[0]), "r"(a[1]), "r"(a[2]), "r"(a[3]), "r"(b0), "r"(b1));
}
__device__ __forceinline__ void split2(float v, __half& h, __half& l) {
    h = __float2half(v);
    l = __float2half(v - __half2float(h));
}

// ---------------- scratch ----------------
#define SZ_R1 (HR_DIM * D_DIM)
#define SZ_E1 (HE_DIM * D_DIM)
#define SZ_F1 (HF_DIM * D_DIM)
#define WOFF_R1 0
#define WOFF_M1 (WOFF_R1 + SZ_R1)
#define WOFF_L1 (WOFF_M1 + SZ_E1)
#define WOFF_M2 (WOFF_L1 + SZ_E1)
#define WOFF_L2 (WOFF_M2 + SZ_E1)
#define WOFF_F1 (WOFF_L2 + SZ_E1)
#define WOFF_F2 (WOFF_F1 + SZ_F1)
#define WPOOL_SZ (WOFF_F2 + SZ_F1)

__device__ __align__(256) __half g_whi[WPOOL_SZ];
__device__ __align__(256) __half g_wlo[SZ_R1];      // lo only for router weights
__device__ __align__(256) __half g_xhi[B_ROWS * D_DIM];
__device__ __align__(256) __half g_xlo[B_ROWS * D_DIM];
__device__ __align__(256) float g_H[B_ROWS * HR_DIM];
__device__ __align__(256) __half g_xehi[ROWS_PAD * D_DIM];
__device__ __align__(256) __half g_y1hi[(size_t)ROWS_PAD * HE_DIM];
__device__ __align__(256) float g_Ff[B_ROWS * D_DIM];
__device__ __align__(256) __half g_fhi[B_ROWS * D_DIM];
__device__ __align__(256) __half g_ghi[B_ROWS * HF_DIM];
__device__ float g_w[B_ROWS];
__device__ int g_hint[B_ROWS];
__device__ int g_list[2 * B_ROWS];
__device__ int g_cnt[2];
__device__ int g_cmap[ROWS_PAD];

// ---------------- merged prep: reset + weight conversion + x conversion ------------
__device__ __forceinline__ void wconv_tile(const float* __restrict__ W,
                                           __half* __restrict__ hi, __half* __restrict__ lo,
                                           int K, int N, int bx, int by) {
    __shared__ float t[32][33];
    int k0 = by * 32, n0 = bx * 32;
    int tx = threadIdx.x, ty = threadIdx.y;
#pragma unroll
    for (int j = 0; j < 4; j++)
        t[ty + j * 8][tx] = W[(size_t)(k0 + ty + j * 8) * N + n0 + tx];
    __syncthreads();
#pragma unroll
    for (int j = 0; j < 4; j++) {
        int n = n0 + ty + j * 8, k = k0 + tx;
        __half h, l;
        split2(t[tx][ty + j * 8], h, l);
        hi[(size_t)n * K + k] = h;
        if (lo) lo[(size_t)n * K + k] = l;
    }
}

#define XCONV_BLOCKS (B_ROWS * D_DIM / 1024)
#define WCONV_BLOCKS (512 + 4 * 4096 + 2 * 2048)
#define PREP_BLOCKS (WCONV_BLOCKS + XCONV_BLOCKS)

__global__ void prep_kernel(const float* W_r1, const float* W_m1, const float* W_l1,
                            const float* W_m2, const float* W_l2,
                            const float* W_f1, const float* W_f2,
                            const float* __restrict__ x) {
    int b = blockIdx.x;
    int tid = threadIdx.y * 32 + threadIdx.x;
    if (b == 0 && tid < 2) g_cnt[tid] = 0;
    if (b >= WCONV_BLOCKS) {
        // x conversion: hi/lo split, 1024 elements per block
        int xb = b - WCONV_BLOCKS;
        size_t i = ((size_t)xb * 256 + tid) * 4;
        float4 v = *(const float4*)(x + i);
        __half h, l;
        split2(v.x, h, l); g_xhi[i] = h;     g_xlo[i] = l;
        split2(v.y, h, l); g_xhi[i + 1] = h; g_xlo[i + 1] = l;
        split2(v.z, h, l); g_xhi[i + 2] = h; g_xlo[i + 2] = l;
        split2(v.w, h, l); g_xhi[i + 3] = h; g_xlo[i + 3] = l;
        return;
    }
    __half* hi = g_whi;
    if (b < 512) { wconv_tile(W_r1, hi + WOFF_R1, g_wlo, D_DIM, HR_DIM, b % 16, b / 16); return; }
    b -= 512;
    if (b < 4096) { wconv_tile(W_m1, hi + WOFF_M1, nullptr, D_DIM, HE_DIM, b % 128, b / 128); return; }
    b -= 4096;
    if (b < 4096) { wconv_tile(W_l1, hi + WOFF_L1, nullptr, D_DIM, HE_DIM, b % 128, b / 128); return; }
    b -= 4096;
    if (b < 4096) { wconv_tile(W_m2, hi + WOFF_M2, nullptr, HE_DIM, D_DIM, b % 32, b / 32); return; }
    b -= 4096;
    if (b < 4096) { wconv_tile(W_l2, hi + WOFF_L2, nullptr, HE_DIM, D_DIM, b % 32, b / 32); return; }
    b -= 4096;
    if (b < 2048) { wconv_tile(W_f1, hi + WOFF_F1, nullptr, D_DIM, HF_DIM, b % 64, b / 64); return; }
    b -= 2048;
    wconv_tile(W_f2, hi + WOFF_F2, nullptr, HF_DIM, D_DIM, b % 32, b / 32);
}

__global__ void router_head_kernel(const float* __restrict__ Wdom, const float* __restrict__ bdom,
                                   const float* __restrict__ Wmop, const float* __restrict__ Wlt) {
    int warp = (blockIdx.x * blockDim.x + threadIdx.x) >> 5;
    int lane = threadIdx.x & 31;
    if (warp >= B_ROWS) return;
    const float* h = g_H + (size_t)warp * HR_DIM;
    float a0 = 0, a1 = 0, m0 = 0, m1 = 0, m2 = 0, m3 = 0, l0 = 0, l1 = 0, l2 = 0, l3 = 0;
    for (int i = lane; i < HR_DIM; i += 32) {
        float hv = h[i];
        a0 += hv * Wdom[i * 2];     a1 += hv * Wdom[i * 2 + 1];
        m0 += hv * Wmop[i * 4];     m1 += hv * Wmop[i * 4 + 1];
        m2 += hv * Wmop[i * 4 + 2]; m3 += hv * Wmop[i * 4 + 3];
        l0 += hv * Wlt[i * 4];      l1 += hv * Wlt[i * 4 + 1];
        l2 += hv * Wlt[i * 4 + 2];  l3 += hv * Wlt[i * 4 + 3];
    }
#pragma unroll
    for (int o = 16; o > 0; o >>= 1) {
        a0 += __shfl_down_sync(~0u, a0, o); a1 += __shfl_down_sync(~0u, a1, o);
        m0 += __shfl_down_sync(~0u, m0, o); m1 += __shfl_down_sync(~0u, m1, o);
        m2 += __shfl_down_sync(~0u, m2, o); m3 += __shfl_down_sync(~0u, m3, o);
        l0 += __shfl_down_sync(~0u, l0, o); l1 += __shfl_down_sync(~0u, l1, o);
        l2 += __shfl_down_sync(~0u, l2, o); l3 += __shfl_down_sync(~0u, l3, o);
    }
    if (lane == 0) {
        a0 += bdom[0]; a1 += bdom[1];
        int primary = (a1 > a0) ? 1 : 0;
        float w = 1.f / (1.f + expf((primary ? a0 : a1) - (primary ? a1 : a0)));
        int mop = 0; float b = m0;
        if (m1 > b) { b = m1; mop = 1; }
        if (m2 > b) { b = m2; mop = 2; }
        if (m3 > b) { b = m3; mop = 3; }
        int lt = 0; b = l0;
        if (l1 > b) { b = l1; lt = 1; }
        if (l2 > b) { b = l2; lt = 2; }
        if (l3 > b) { b = l3; lt = 3; }
        g_w[warp] = w;
        g_hint[warp] = primary ? lt : mop;
        int pos = atomicAdd(&g_cnt[primary], 1);
        g_list[primary * B_ROWS + pos] = warp;
    }
}

__global__ void gather_kernel(const float* __restrict__ x, const float* __restrict__ op_emb,
                              const float* __restrict__ task_emb) {
    int bidx = blockIdx.x;
    int c0 = g_cnt[0], c1 = g_cnt[1];
    int A0 = ((c0 + 127) >> 7) << 7;
    int orig = -1;
    const float* er = nullptr;
    if (bidx < c0) {
        orig = g_list[bidx];
        er = op_emb + (size_t)g_hint[orig] * D_DIM;
    } else if (bidx >= A0 && bidx < A0 + c1) {
        orig = g_list[B_ROWS + bidx - A0];
        er = task_emb + (size_t)g_hint[orig] * D_DIM;
    }
    if (threadIdx.x == 0) g_cmap[bidx] = orig;
    if (orig < 0) return;
    const float* xr = x + (size_t)orig * D_DIM;
    size_t ob = (size_t)bidx * D_DIM;
    for (int i = threadIdx.x * 4; i < D_DIM; i += 512) {
        float4 xv = *(const float4*)(xr + i);
        float4 ev = *(const float4*)(er + i);
        __half2 h01, h23;
        h01.x = __float2half(xv.x + ev.x);
        h01.y = __float2half(xv.y + ev.y);
        h23.x = __float2half(xv.z + ev.z);
        h23.y = __float2half(xv.w + ev.w);
        *(__half2*)(g_xehi + ob + i)     = h01;
        *(__half2*)(g_xehi + ob + i + 2) = h23;
    }
}

// ---------------- HMMA fp16 GEMM: 128x256 tile, 2-slot 96KB stages ----------------
// MODE 0 (router): BK=64; stage = A-hi 16K | A-lo 16K | B-hi 32K | B-lo 32K; 3 passes.
// MODE 2 (others): BK=128; stage = A-hi 32K (256B rows) | B 64K (256B rows); 1 pass.
template <bool RELU, bool SCAT, bool RESID, bool WF32, bool WBF, bool MERGE, int MODE>
__global__ void __launch_bounds__(512, 1) mm_hmma(
    const __half* __restrict__ Ahi, const __half* __restrict__ Alo,
    const __half* __restrict__ Bhi, const __half* __restrict__ Blo,
    const __half* __restrict__ B2hi,
    const float* __restrict__ bias, const float* __restrict__ bias2,
    float* __restrict__ Cf, __half* __restrict__ Chi,
    const float* __restrict__ resid, int N, int K) {
    constexpr int ROWB   = (MODE == 0) ? 128 : 256;
    constexpr int ABYTES = 32768;
    constexpr int STAGE  = 98304;
    constexpr int BKSH   = (MODE == 0) ? 6 : 7;
    constexpr int NKS    = (MODE == 0) ? 4 : 8;

    const int m0 = blockIdx.y * 128;
    if (MERGE) {
        int A0 = ((g_cnt[0] + 127) >> 7) << 7;
        if (m0 >= A0 + g_cnt[1]) return;
        if (m0 >= A0) { Bhi = B2hi; bias = bias2; }
    }
    const int n0 = blockIdx.x * 256;
    const int tid = threadIdx.x;
    const int lane = tid & 31, wid = tid >> 5;
    const int wm = wid & 3, wn = wid >> 2;  // 4x4 warp grid: warp tile 32x64

    extern __shared__ char sm_raw[];
    char* sm = (char*)(((uintptr_t)sm_raw + 127) & ~(uintptr_t)127);
    const uint32_t sbase = smem_u32(sm);

    float acc[2][8][4];
#pragma unroll
    for (int a = 0; a < 2; a++)
#pragma unroll
        for (int b = 0; b < 8; b++)
#pragma unroll
            for (int c = 0; c < 4; c++) acc[a][b][c] = 0.f;

    const int niter = K >> BKSH;

    auto issue = [&](int it) {
        const int slot = it & 1;
        const int k0 = it << BKSH;
        const uint32_t as = sbase + slot * STAGE;
        const uint32_t bs = as + ABYTES;
        if (MODE == 0) {
            // A-hi + A-lo: 128 rows x 8 chunks each = 2 x 1024 cp16
#pragma unroll
            for (int rep = 0; rep < 2; rep++) {
                int c = rep * 512 + tid;
                int r = c >> 3, j = c & 7;
                uint32_t loc = (uint32_t)(r * 128 + ((j * 16) ^ ((r & 7) << 4)));
                cp16(as + loc, Ahi + (size_t)(m0 + r) * K + k0 + j * 8);
                cp16(as + 16384u + loc, Alo + (size_t)(m0 + r) * K + k0 + j * 8);
            }
            // B-hi + B-lo: 256 rows x 8 chunks each = 2 x 2048 cp16
#pragma unroll
            for (int rep = 0; rep < 4; rep++) {
                int c = rep * 512 + tid;
                int r = c >> 3, j = c & 7;
                uint32_t loc = (uint32_t)(r * 128 + ((j * 16) ^ ((r & 7) << 4)));
                cp16(bs + loc, Bhi + (size_t)(n0 + r) * K + k0 + j * 8);
                cp16(bs + 32768u + loc, Blo + (size_t)(n0 + r) * K + k0 + j * 8);
            }
        } else {
            // A hi only, 256B rows: 2048 cp16
#pragma unroll
            for (int rep = 0; rep < 4; rep++) {
                int c = rep * 512 + tid;
                int r = c >> 4, j = c & 15;
                uint32_t loc = (uint32_t)(r * 256 + ((j * 16) ^ ((r & 7) << 4)));
                cp16(as + loc, Ahi + (size_t)(m0 + r) * K + k0 + j * 8);
            }
            // B single, 256B rows: 4096 cp16
#pragma unroll
            for (int rep = 0; rep < 8; rep++) {
                int c = rep * 512 + tid;
                int r = c >> 4, j = c & 15;
                uint32_t loc = (uint32_t)(r * 256 + ((j * 16) ^ ((r & 7) << 4)));
                cp16(bs + loc, Bhi + (size_t)(n0 + r) * K + k0 + j * 8);
            }
        }
    };

    auto compute = [&](int slot) {
        const uint32_t as = sbase + slot * STAGE;
        const uint32_t bs = as + ABYTES;
#pragma unroll
        for (int ks = 0; ks < NKS; ks++) {
            const int kb = ks * 32;
            uint32_t ah[2][4], al[2][4], bq[4][4];
#pragma unroll
            for (int mt = 0; mt < 2; mt++) {
                int r = wm * 32 + mt * 16 + (lane & 15);
                int sw = (r & 7) << 4;
                uint32_t rb = as + r * ROWB;
                int bo = kb + ((lane >> 4) << 4);
                ldsm4(ah[mt][0], ah[mt][1], ah[mt][2], ah[mt][3], rb + (uint32_t)(bo ^ sw));
                if (MODE == 0)
                    ldsm4(al[mt][0], al[mt][1], al[mt][2], al[mt][3],
                          rb + 16384u + (uint32_t)(bo ^ sw));
            }
#pragma unroll
            for (int np = 0; np < 4; np++) {
                int r = wn * 64 + np * 16 + (lane & 7) + ((lane >> 4) << 3);
                int sw = (r & 7) << 4;
                int bo = kb + (((lane >> 3) & 1) << 4);
                ldsm4(bq[np][0], bq[np][1], bq[np][2], bq[np][3],
                      bs + r * ROWB + (uint32_t)(bo ^ sw));
            }
            // pass: ah x b
#pragma unroll
            for (int np = 0; np < 4; np++)
#pragma unroll
                for (int mt = 0; mt < 2; mt++) {
                    mma16816(acc[mt][np * 2],     ah[mt], bq[np][0], bq[np][1]);
                    mma16816(acc[mt][np * 2 + 1], ah[mt], bq[np][2], bq[np][3]);
                }
            if (MODE == 0) {
                // pass: al x bh
#pragma unroll
                for (int np = 0; np < 4; np++)
#pragma unroll
                    for (int mt = 0; mt < 2; mt++) {
                        mma16816(acc[mt][np * 2],     al[mt], bq[np][0], bq[np][1]);
                        mma16816(acc[mt][np * 2 + 1], al[mt], bq[np][2], bq[np][3]);
                    }
                // B-lo + pass: ah x bl
#pragma unroll
                for (int np = 0; np < 4; np++) {
                    int r = wn * 64 + np * 16 + (lane & 7) + ((lane >> 4) << 3);
                    int sw = (r & 7) << 4;
                    int bo = kb + (((lane >> 3) & 1) << 4);
                    ldsm4(bq[np][0], bq[np][1], bq[np][2], bq[np][3],
                          bs + 32768u + r * 128 + (uint32_t)(bo ^ sw));
                }
#pragma unroll
                for (int np = 0; np < 4; np++)
#pragma unroll
                    for (int mt = 0; mt < 2; mt++) {
                        mma16816(acc[mt][np * 2],     ah[mt], bq[np][0], bq[np][1]);
                        mma16816(acc[mt][np * 2 + 1], ah[mt], bq[np][2], bq[np][3]);
                    }
            }
        }
    };

    // 2-slot pipeline: copy of i+1 overlaps compute(i)
    issue(0); CP_COMMIT;
    CP_WAIT0;
    __syncthreads();
    for (int i = 0; i < niter; i++) {
        if (i + 1 < niter) { issue(i + 1); CP_COMMIT; }
        compute(i & 1);
        if (i + 1 < niter) { CP_WAIT0; }
        __syncthreads();
    }

    // ---- epilogue ----
    const int tg = lane & 3, g = lane >> 2;
#pragma unroll
    for (int mt = 0; mt < 2; mt++) {
#pragma unroll
        for (int h2 = 0; h2 < 2; h2++) {
            int row = m0 + wm * 32 + mt * 16 + g + h2 * 8;
            int orig = row;
            float wsc = 1.f;
            bool valid = true;
            if (SCAT) {
                orig = g_cmap[row];
                valid = orig >= 0;
                wsc = valid ? g_w[orig] : 0.f;
            }
            if (!valid) continue;
            size_t rowoff = (size_t)orig * N;
#pragma unroll
            for (int nt = 0; nt < 8; nt++) {
                int col = n0 + wn * 64 + nt * 8 + tg * 2;
                float v0 = acc[mt][nt][h2 * 2]     + bias[col];
                float v1 = acc[mt][nt][h2 * 2 + 1] + bias[col + 1];
                if (RELU) { v0 = fmaxf(v0, 0.f); v1 = fmaxf(v1, 0.f); }
                if (SCAT) { v0 *= wsc; v1 *= wsc; }
                if (RESID) {
                    float2 rv = *(const float2*)(resid + rowoff + col);
                    v0 += rv.x; v1 += rv.y;
                }
                if (WF32) {
                    float2 o; o.x = v0; o.y = v1;
                    *(float2*)(Cf + rowoff + col) = o;
                }
                if (WBF) {
                    __half2 hh;
                    hh.x = __float2half(v0);
                    hh.y = __float2half(v1);
                    *(__half2*)(Chi + rowoff + col) = hh;
                }
            }
        }
    }
}

#define DYN_SMEM (2 * 98304 + 128)

// ---------------- launch ----------------
extern "C" void kernel_launch(void* const* d_in, const int* in_sizes, int n_in,
                              void* d_out, int out_size) {
    const float* x        = (const float*)d_in[0];
    const float* W_r1     = (const float*)d_in[1];
    const float* b_r1     = (const float*)d_in[2];
    const float* W_dom    = (const float*)d_in[3];
    const float* b_dom    = (const float*)d_in[4];
    const float* W_mop    = (const float*)d_in[5];
    const float* W_lt     = (const float*)d_in[6];
    const float* op_emb   = (const float*)d_in[7];
    const float* W_m1     = (const float*)d_in[8];
    const float* b_m1     = (const float*)d_in[9];
    const float* W_m2     = (const float*)d_in[10];
    const float* b_m2     = (const float*)d_in[11];
    const float* task_emb = (const float*)d_in[12];
    const float* W_l1     = (const float*)d_in[13];
    const float* b_l1     = (const float*)d_in[14];
    const float* W_l2     = (const float*)d_in[15];
    const float* b_l2     = (const float*)d_in[16];
    const float* W_f1     = (const float*)d_in[17];
    const float* b_f1     = (const float*)d_in[18];
    const float* W_f2     = (const float*)d_in[19];
    const float* b_f2     = (const float*)d_in[20];
    float* out = (float*)d_out;

    __half *whi, *wlo, *xhi, *xlo, *xehi, *y1hi, *fhi, *ghi;
    float *H, *Ff;
    cudaGetSymbolAddress((void**)&whi, g_whi);
    cudaGetSymbolAddress((void**)&wlo, g_wlo);
    cudaGetSymbolAddress((void**)&xhi, g_xhi);
    cudaGetSymbolAddress((void**)&xlo, g_xlo);
    cudaGetSymbolAddress((void**)&xehi, g_xehi);
    cudaGetSymbolAddress((void**)&y1hi, g_y1hi);
    cudaGetSymbolAddress((void**)&fhi, g_fhi);
    cudaGetSymbolAddress((void**)&ghi, g_ghi);
    cudaGetSymbolAddress((void**)&H, g_H);
    cudaGetSymbolAddress((void**)&Ff, g_Ff);

    cudaFuncSetAttribute(
        (const void*)mm_hmma<true, false, false, true, false, false, 0>,
        cudaFuncAttributeMaxDynamicSharedMemorySize, DYN_SMEM);
    cudaFuncSetAttribute(
        (const void*)mm_hmma<true, false, false, false, true, true, 2>,
        cudaFuncAttributeMaxDynamicSharedMemorySize, DYN_SMEM);
    cudaFuncSetAttribute(
        (const void*)mm_hmma<false, true, false, true, true, true, 2>,
        cudaFuncAttributeMaxDynamicSharedMemorySize, DYN_SMEM);
    cudaFuncSetAttribute(
        (const void*)mm_hmma<true, false, false, false, true, false, 2>,
        cudaFuncAttributeMaxDynamicSharedMemorySize, DYN_SMEM);
    cudaFuncSetAttribute(
        (const void*)mm_hmma<false, false, true, true, false, false, 2>,
        cudaFuncAttributeMaxDynamicSharedMemorySize, DYN_SMEM);

    dim3 blk(512);
    int mtiles = B_ROWS / 128;
    int mtiles_pad = ROWS_PAD / 128;

    // prep: reset counters + weight hi/lo conversion + x hi/lo conversion (one launch)
    prep_kernel<<<PREP_BLOCKS, dim3(32, 8)>>>(W_r1, W_m1, W_l1, W_m2, W_l2, W_f1, W_f2, x);

    // router (MODE0, fp16x3, BK=64 — argmax-safe): H = relu(x @ W_r1 + b_r1)
    mm_hmma<true, false, false, true, false, false, 0>
        <<<dim3(HR_DIM / 256, mtiles), blk, DYN_SMEM>>>(
        xhi, xlo, whi + WOFF_R1, wlo, nullptr, b_r1, nullptr,
        H, nullptr, nullptr, HR_DIM, D_DIM);
    router_head_kernel<<<B_ROWS / 8, 256>>>(W_dom, b_dom, W_mop, W_lt);
    gather_kernel<<<ROWS_PAD, 128>>>(x, op_emb, task_emb);

    // expert layer 1 (MODE2 merged, BK=128): Y1 = relu(XE @ W1 + b1)
    mm_hmma<true, false, false, false, true, true, 2>
        <<<dim3(HE_DIM / 256, mtiles_pad), blk, DYN_SMEM>>>(
        xehi, nullptr, whi + WOFF_M1, nullptr, whi + WOFF_L1, b_m1, b_l1,
        nullptr, y1hi, nullptr, HE_DIM, D_DIM);
    // expert layer 2 (MODE2 merged, scatter, BK=128): FUSED = w*(Y1 @ W2 + b2)
    mm_hmma<false, true, false, true, true, true, 2>
        <<<dim3(D_DIM / 256, mtiles_pad), blk, DYN_SMEM>>>(
        y1hi, nullptr, whi + WOFF_M2, nullptr, whi + WOFF_L2, b_m2, b_l2,
        Ff, fhi, nullptr, D_DIM, HE_DIM);
    // fusion layer 1 (MODE2, BK=128): G = relu(FUSED @ W_f1 + b_f1)
    mm_hmma<true, false, false, false, true, false, 2>
        <<<dim3(HF_DIM / 256, mtiles), blk, DYN_SMEM>>>(
        fhi, nullptr, whi + WOFF_F1, nullptr, nullptr, b_f1, nullptr,
        nullptr, ghi, nullptr, HF_DIM, D_DIM);
    // fusion layer 2 (MODE2, BK=128): out = FUSED + G @ W_f2 + b_f2
    mm_hmma<false, false, true, true, false, false, 2>
        <<<dim3(D_DIM / 256, mtiles), blk, DYN_SMEM>>>(
        ghi, nullptr, whi + WOFF_F2, nullptr, nullptr, b_f2, nullptr,
        out, nullptr, Ff, D_DIM, HF_DIM);
}